// round 6
// baseline (speedup 1.0000x reference)
#include <cuda_runtime.h>
#include <cuda_fp16.h>

#define N_NODES 100000
#define N_EDGES 1600000
#define F 128
#define NB_SCAN 98            // ceil(100000/1024)

typedef unsigned long long u64;

// ---------------- scratch (static __device__, no allocation) ----------------
__device__ int   g_deg_out_i[N_NODES];
__device__ int   g_deg_in_i[N_NODES];
__device__ float g_rs_out[N_NODES];
__device__ float g_rs_in[N_NODES];
__device__ int   g_rowp[N_NODES + 1];     // CSR row pointers (by dst)
__device__ int   g_cursor[N_NODES];       // fill cursors
__device__ int   g_csr[N_EDGES];          // src indices grouped by dst
__device__ int   g_bsum[NB_SCAN];
__device__ float g_y[(size_t)N_NODES * 2];
__device__ __align__(16) __half g_xh[(size_t)N_NODES * F];  // fp16(x * rs_out)

// ---------------- packed fp32x2 helpers --------------------------------------
__device__ __forceinline__ u64 pack2(float x, float y) {
    u64 r; asm("mov.b64 %0,{%1,%2};" : "=l"(r) : "f"(x), "f"(y)); return r;
}
__device__ __forceinline__ void unpack2(u64 v, float& x, float& y) {
    asm("mov.b64 {%0,%1},%2;" : "=f"(x), "=f"(y) : "l"(v));
}
__device__ __forceinline__ u64 fma2(u64 a, u64 b, u64 c) {
    u64 d; asm("fma.rn.f32x2 %0,%1,%2,%3;" : "=l"(d) : "l"(a), "l"(b), "l"(c)); return d;
}

// ---------------- zero counters ----------------------------------------------
__global__ void k_zero() {
    int i = blockIdx.x * blockDim.x + threadIdx.x;
    if (i < N_NODES) { g_deg_out_i[i] = 0; g_deg_in_i[i] = 0; }
}

// ---------------- degrees (int histogram, 2 edges/thread) --------------------
__global__ void k_deg(const int2* __restrict__ src2, const int2* __restrict__ dst2) {
    int i = blockIdx.x * blockDim.x + threadIdx.x;
    if (i < N_EDGES / 2) {
        int2 s = src2[i], d = dst2[i];
        atomicAdd(&g_deg_out_i[s.x], 1);
        atomicAdd(&g_deg_out_i[s.y], 1);
        atomicAdd(&g_deg_in_i[d.x], 1);
        atomicAdd(&g_deg_in_i[d.y], 1);
    }
}

// ---------------- block scan of deg_in (warp-shuffle) + rs -------------------
__global__ void k_scan_block() {
    __shared__ int wsum[32];
    int tid = threadIdx.x, lane = tid & 31, wid = tid >> 5;
    int gid = blockIdx.x * 1024 + tid;
    int v = (gid < N_NODES) ? g_deg_in_i[gid] : 0;
    int x = v;
    #pragma unroll
    for (int off = 1; off < 32; off <<= 1) {
        int t = __shfl_up_sync(0xffffffffu, x, off);
        if (lane >= off) x += t;
    }
    if (lane == 31) wsum[wid] = x;
    __syncthreads();
    if (wid == 0) {
        int s = wsum[lane];
        #pragma unroll
        for (int off = 1; off < 32; off <<= 1) {
            int t = __shfl_up_sync(0xffffffffu, s, off);
            if (lane >= off) s += t;
        }
        wsum[lane] = s;
    }
    __syncthreads();
    int inc = x + (wid ? wsum[wid - 1] : 0);
    if (gid < N_NODES) {
        g_rowp[gid + 1] = inc;                         // inclusive, pre-offset
        g_rs_in[gid]  = rsqrtf(fmaxf((float)v, 1.0f));
        g_rs_out[gid] = rsqrtf(fmaxf((float)g_deg_out_i[gid], 1.0f));
    }
    if (tid == 1023) g_bsum[blockIdx.x] = inc;
}

// ---------------- finalize scan: per-block offset reduce + add-back ----------
__global__ void k_scan_fin() {                         // grid NB_SCAN, block 1024
    __shared__ int wred[32];
    __shared__ int s_off;
    int tid = threadIdx.x, lane = tid & 31, wid = tid >> 5;
    int bid = blockIdx.x;
    int v = (tid < bid) ? g_bsum[tid] : 0;             // bid <= 97 < 1024
    #pragma unroll
    for (int off = 16; off; off >>= 1) v += __shfl_xor_sync(0xffffffffu, v, off);
    if (lane == 0) wred[wid] = v;
    __syncthreads();
    if (wid == 0) {
        int t = wred[lane];
        #pragma unroll
        for (int off = 16; off; off >>= 1) t += __shfl_xor_sync(0xffffffffu, t, off);
        if (lane == 0) s_off = t;
    }
    __syncthreads();
    int off = s_off;
    int gid = bid * 1024 + tid;
    if (gid < N_NODES) {
        int val = g_rowp[gid + 1] + off;
        g_rowp[gid + 1] = val;
        if (gid + 1 < N_NODES) g_cursor[gid + 1] = val;
        if (gid == 0) { g_rowp[0] = 0; g_cursor[0] = 0; }
    }
}

// ---------------- x -> fp16(x * rs_out), vectorized --------------------------
// i over N_NODES*16: two consecutive float4 in, one uint4 (8 halves) out.
// Both float4 belong to the same node (2i and 2i+1 share i>>4... proven: 2i+1
// is odd, row boundary is a multiple of 32).
__global__ void k_tohalf(const float4* __restrict__ x4) {
    int i = blockIdx.x * blockDim.x + threadIdx.x;
    if (i < N_NODES * 16) {
        int j0 = i * 2;
        float c = g_rs_out[j0 >> 5];
        float4 v0 = x4[j0], v1 = x4[j0 + 1];
        __half2 h0 = __floats2half2_rn(v0.x * c, v0.y * c);
        __half2 h1 = __floats2half2_rn(v0.z * c, v0.w * c);
        __half2 h2 = __floats2half2_rn(v1.x * c, v1.y * c);
        __half2 h3 = __floats2half2_rn(v1.z * c, v1.w * c);
        ((uint4*)g_xh)[i] = make_uint4(*(unsigned*)&h0, *(unsigned*)&h1,
                                       *(unsigned*)&h2, *(unsigned*)&h3);
    }
}

// ---------------- CSR bucket fill (2 edges/thread) ---------------------------
__global__ void k_fill(const int2* __restrict__ src2, const int2* __restrict__ dst2) {
    int i = blockIdx.x * blockDim.x + threadIdx.x;
    if (i < N_EDGES / 2) {
        int2 s = src2[i], d = dst2[i];
        int p0 = atomicAdd(&g_cursor[d.x], 1);
        g_csr[p0] = s.x;
        int p1 = atomicAdd(&g_cursor[d.y], 1);
        g_csr[p1] = s.y;
    }
}

// ---------------- fused layer-1 ----------------------------------------------
// Gather (fp16, fp32 accum) -> stage duplicated activations in warp-private
// smem -> f32x2 GEMM (no shfl, no per-step pack) -> relu -> W2 -> y.
// smem: W1 64KB | b1 512B | W2 1KB | a_dup 32KB  (99840 B total)
__global__ void __launch_bounds__(256) k_fused1(const float* __restrict__ W1,
                                                const float* __restrict__ b1,
                                                const float* __restrict__ W2) {
    extern __shared__ float smem[];
    ulonglong2* Wsu  = (ulonglong2*)smem;              // W1[k][c] as 2x f32x2
    float4*     Ws4  = (float4*)smem;
    float4*     b1s4 = (float4*)(smem + 16384);        // 32 float4
    float2*     W2s  = (float2*)(smem + 16384 + 128);  // 128 float2
    float2*     adup = (float2*)(smem + 16384 + 128 + 256); // 4096 float2

    int tid = threadIdx.x;
    const float4* W14 = (const float4*)W1;
    #pragma unroll
    for (int i = 0; i < 16; i++) Ws4[tid + i * 256] = W14[tid + i * 256];
    if (tid < 32)  b1s4[tid] = ((const float4*)b1)[tid];
    if (tid < 128) W2s[tid]  = ((const float2*)W2)[tid];
    __syncthreads();

    int warp = tid >> 5, lane = tid & 31;
    int i0 = blockIdx.x * 32 + warp * 4;               // 3125 * 32 = 100000
    float2* aw = adup + warp * 512;                    // warp-private 4x128 f32x2

    const uint2* xh2 = (const uint2*)g_xh;             // 4 halves per lane

    // --- gather per node; immediately stage duplicated values to smem ---
    #pragma unroll
    for (int m = 0; m < 4; m++) {
        int node = i0 + m;
        int beg = __ldg(&g_rowp[node]), end = __ldg(&g_rowp[node + 1]);
        float4 acc = make_float4(0.f, 0.f, 0.f, 0.f);
        int e = beg;
        for (; e + 4 <= end; e += 4) {
            int s0 = __ldg(&g_csr[e]),     s1 = __ldg(&g_csr[e + 1]);
            int s2 = __ldg(&g_csr[e + 2]), s3 = __ldg(&g_csr[e + 3]);
            uint2 v0 = xh2[s0 * 32 + lane];
            uint2 v1 = xh2[s1 * 32 + lane];
            uint2 v2 = xh2[s2 * 32 + lane];
            uint2 v3 = xh2[s3 * 32 + lane];
            float2 f;
            f = __half22float2(*(__half2*)&v0.x); acc.x += f.x; acc.y += f.y;
            f = __half22float2(*(__half2*)&v0.y); acc.z += f.x; acc.w += f.y;
            f = __half22float2(*(__half2*)&v1.x); acc.x += f.x; acc.y += f.y;
            f = __half22float2(*(__half2*)&v1.y); acc.z += f.x; acc.w += f.y;
            f = __half22float2(*(__half2*)&v2.x); acc.x += f.x; acc.y += f.y;
            f = __half22float2(*(__half2*)&v2.y); acc.z += f.x; acc.w += f.y;
            f = __half22float2(*(__half2*)&v3.x); acc.x += f.x; acc.y += f.y;
            f = __half22float2(*(__half2*)&v3.y); acc.z += f.x; acc.w += f.y;
        }
        for (; e < end; ++e) {
            int s0 = __ldg(&g_csr[e]);
            uint2 v0 = xh2[s0 * 32 + lane];
            float2 f;
            f = __half22float2(*(__half2*)&v0.x); acc.x += f.x; acc.y += f.y;
            f = __half22float2(*(__half2*)&v0.y); acc.z += f.x; acc.w += f.y;
        }
        float ri = g_rs_in[node];
        float2* am = aw + m * 128 + 4 * lane;
        am[0] = make_float2(acc.x * ri, acc.x * ri);
        am[1] = make_float2(acc.y * ri, acc.y * ri);
        am[2] = make_float2(acc.z * ri, acc.z * ri);
        am[3] = make_float2(acc.w * ri, acc.w * ri);
    }
    __syncwarp();

    // --- W1 GEMM, f32x2: acc[m].{xy,zw} += a_dup[m][k] * W1[k][cols] ---
    u64 accxy[4], acczw[4];
    {
        float4 bb = b1s4[lane];
        u64 bxy = pack2(bb.x, bb.y), bzw = pack2(bb.z, bb.w);
        #pragma unroll
        for (int m = 0; m < 4; m++) { accxy[m] = bxy; acczw[m] = bzw; }
    }
    const u64* awu = (const u64*)aw;
    #pragma unroll 8
    for (int k = 0; k < 128; ++k) {
        ulonglong2 wv = Wsu[k * 32 + lane];            // (w.x,w.y) (w.z,w.w)
        u64 a0 = awu[k];
        u64 a1 = awu[128 + k];
        u64 a2 = awu[256 + k];
        u64 a3 = awu[384 + k];
        accxy[0] = fma2(wv.x, a0, accxy[0]); acczw[0] = fma2(wv.y, a0, acczw[0]);
        accxy[1] = fma2(wv.x, a1, accxy[1]); acczw[1] = fma2(wv.y, a1, acczw[1]);
        accxy[2] = fma2(wv.x, a2, accxy[2]); acczw[2] = fma2(wv.y, a2, acczw[2]);
        accxy[3] = fma2(wv.x, a3, accxy[3]); acczw[3] = fma2(wv.y, a3, acczw[3]);
    }

    // --- relu + W2 (128x2) projection, warp-reduce, *rs_out -> y ---
    float2 w0 = W2s[4 * lane + 0], w1 = W2s[4 * lane + 1];
    float2 w2 = W2s[4 * lane + 2], w3 = W2s[4 * lane + 3];
    float p0[4], p1[4];
    #pragma unroll
    for (int m = 0; m < 4; m++) {
        float h0, h1, h2, h3;
        unpack2(accxy[m], h0, h1);
        unpack2(acczw[m], h2, h3);
        h0 = fmaxf(h0, 0.f); h1 = fmaxf(h1, 0.f);
        h2 = fmaxf(h2, 0.f); h3 = fmaxf(h3, 0.f);
        p0[m] = h0 * w0.x + h1 * w1.x + h2 * w2.x + h3 * w3.x;
        p1[m] = h0 * w0.y + h1 * w1.y + h2 * w2.y + h3 * w3.y;
    }
    #pragma unroll
    for (int off = 16; off; off >>= 1) {
        #pragma unroll
        for (int m = 0; m < 4; m++) {
            p0[m] += __shfl_xor_sync(0xffffffffu, p0[m], off);
            p1[m] += __shfl_xor_sync(0xffffffffu, p1[m], off);
        }
    }
    if (lane == 0) {
        float2* y2 = (float2*)g_y;
        #pragma unroll
        for (int m = 0; m < 4; m++) {
            float ro = g_rs_out[i0 + m];
            y2[i0 + m] = make_float2(p0[m] * ro, p1[m] * ro);
        }
    }
}

// ---------------- layer-2: CSR gather of y + finalize ------------------------
__global__ void k_out(float* __restrict__ out, const float* __restrict__ b2) {
    int i = blockIdx.x * blockDim.x + threadIdx.x;
    if (i >= N_NODES) return;
    int beg = __ldg(&g_rowp[i]), end = __ldg(&g_rowp[i + 1]);
    const float2* y2 = (const float2*)g_y;
    float s0 = 0.f, s1 = 0.f;
    int e = beg;
    for (; e + 2 <= end; e += 2) {
        int a = __ldg(&g_csr[e]), b = __ldg(&g_csr[e + 1]);
        float2 va = y2[a], vb = y2[b];
        s0 += va.x + vb.x;
        s1 += va.y + vb.y;
    }
    if (e < end) {
        float2 va = y2[__ldg(&g_csr[e])];
        s0 += va.x; s1 += va.y;
    }
    float ri = g_rs_in[i];
    ((float2*)out)[i] = make_float2(s0 * ri + __ldg(&b2[0]),
                                    s1 * ri + __ldg(&b2[1]));
}

// ---------------- launch ------------------------------------------------------
extern "C" void kernel_launch(void* const* d_in, const int* in_sizes, int n_in,
                              void* d_out, int out_size) {
    const float* in_feat = (const float*)d_in[0];
    const int*   src     = (const int*)d_in[1];
    const int*   dst     = (const int*)d_in[2];
    const float* W1      = (const float*)d_in[3];
    const float* b1      = (const float*)d_in[4];
    const float* W2      = (const float*)d_in[5];
    const float* b2      = (const float*)d_in[6];
    float*       out     = (float*)d_out;

    const int T = 256;
    const int SMEM_NODE = (16384 + 128 + 256 + 8192) * (int)sizeof(float); // 99840 B
    cudaFuncSetAttribute(k_fused1, cudaFuncAttributeMaxDynamicSharedMemorySize, SMEM_NODE);

    k_zero<<<(N_NODES + T - 1) / T, T>>>();
    k_deg<<<(N_EDGES / 2 + T - 1) / T, T>>>((const int2*)src, (const int2*)dst);
    k_scan_block<<<NB_SCAN, 1024>>>();
    k_tohalf<<<(N_NODES * 16 + T - 1) / T, T>>>((const float4*)in_feat);
    k_scan_fin<<<NB_SCAN, 1024>>>();
    k_fill<<<(N_EDGES / 2 + T - 1) / T, T>>>((const int2*)src, (const int2*)dst);
    k_fused1<<<N_NODES / 32, T, SMEM_NODE>>>(W1, b1, W2);
    k_out<<<(N_NODES + T - 1) / T, T>>>(out, b2);
}

// round 7
// speedup vs baseline: 1.2437x; 1.2437x over previous
#include <cuda_runtime.h>
#include <cuda_fp16.h>

#define N_NODES 100000
#define N_EDGES 1600000
#define F 128
#define NB_SCAN 98            // ceil(100000/1024)
#define TB_F1 384             // fused1 block size (12 warps, 48 nodes/block)
#define NB_F1 2084            // ceil(100000/48)

// ---------------- scratch (static __device__, no allocation) ----------------
__device__ int   g_deg_out_i[N_NODES];
__device__ int   g_deg_in_i[N_NODES];
__device__ float g_rs_out[N_NODES];
__device__ float g_rs_in[N_NODES];
__device__ int   g_rowp[N_NODES + 1];     // CSR row pointers (by dst)
__device__ int   g_cursor[N_NODES];       // fill cursors
__device__ int   g_csr[N_EDGES];          // src indices grouped by dst
__device__ int   g_bsum[NB_SCAN];
__device__ float g_y[(size_t)N_NODES * 2];
__device__ __align__(16) __half g_xh[(size_t)N_NODES * F];  // fp16(x * rs_out)

// ---------------- zero counters ----------------------------------------------
__global__ void k_zero() {
    int i = blockIdx.x * blockDim.x + threadIdx.x;
    if (i < N_NODES) { g_deg_out_i[i] = 0; g_deg_in_i[i] = 0; }
}

// ---------------- degrees (int histogram, 2 edges/thread) --------------------
__global__ void k_deg(const int2* __restrict__ src2, const int2* __restrict__ dst2) {
    int i = blockIdx.x * blockDim.x + threadIdx.x;
    if (i < N_EDGES / 2) {
        int2 s = src2[i], d = dst2[i];
        atomicAdd(&g_deg_out_i[s.x], 1);
        atomicAdd(&g_deg_out_i[s.y], 1);
        atomicAdd(&g_deg_in_i[d.x], 1);
        atomicAdd(&g_deg_in_i[d.y], 1);
    }
}

// ---------------- block scan of deg_in (warp-shuffle) + rs -------------------
__global__ void k_scan_block() {
    __shared__ int wsum[32];
    int tid = threadIdx.x, lane = tid & 31, wid = tid >> 5;
    int gid = blockIdx.x * 1024 + tid;
    int v = (gid < N_NODES) ? g_deg_in_i[gid] : 0;
    int x = v;
    #pragma unroll
    for (int off = 1; off < 32; off <<= 1) {
        int t = __shfl_up_sync(0xffffffffu, x, off);
        if (lane >= off) x += t;
    }
    if (lane == 31) wsum[wid] = x;
    __syncthreads();
    if (wid == 0) {
        int s = wsum[lane];
        #pragma unroll
        for (int off = 1; off < 32; off <<= 1) {
            int t = __shfl_up_sync(0xffffffffu, s, off);
            if (lane >= off) s += t;
        }
        wsum[lane] = s;
    }
    __syncthreads();
    int inc = x + (wid ? wsum[wid - 1] : 0);
    if (gid < N_NODES) {
        g_rowp[gid + 1] = inc;                         // inclusive, pre-offset
        g_rs_in[gid]  = rsqrtf(fmaxf((float)v, 1.0f));
        g_rs_out[gid] = rsqrtf(fmaxf((float)g_deg_out_i[gid], 1.0f));
    }
    if (tid == 1023) g_bsum[blockIdx.x] = inc;
}

// ---------------- finalize scan: per-block offset reduce + add-back ----------
__global__ void k_scan_fin() {                         // grid NB_SCAN, block 1024
    __shared__ int wred[32];
    __shared__ int s_off;
    int tid = threadIdx.x, lane = tid & 31, wid = tid >> 5;
    int bid = blockIdx.x;
    int v = (tid < bid) ? g_bsum[tid] : 0;             // bid <= 97 < 1024
    #pragma unroll
    for (int off = 16; off; off >>= 1) v += __shfl_xor_sync(0xffffffffu, v, off);
    if (lane == 0) wred[wid] = v;
    __syncthreads();
    if (wid == 0) {
        int t = wred[lane];
        #pragma unroll
        for (int off = 16; off; off >>= 1) t += __shfl_xor_sync(0xffffffffu, t, off);
        if (lane == 0) s_off = t;
    }
    __syncthreads();
    int off = s_off;
    int gid = bid * 1024 + tid;
    if (gid < N_NODES) {
        int val = g_rowp[gid + 1] + off;
        g_rowp[gid + 1] = val;
        if (gid + 1 < N_NODES) g_cursor[gid + 1] = val;
        if (gid == 0) { g_rowp[0] = 0; g_cursor[0] = 0; }
    }
}

// ---------------- x -> fp16(x * rs_out), vectorized --------------------------
__global__ void k_tohalf(const float4* __restrict__ x4) {
    int i = blockIdx.x * blockDim.x + threadIdx.x;
    if (i < N_NODES * 16) {
        int j0 = i * 2;
        float c = g_rs_out[j0 >> 5];
        float4 v0 = x4[j0], v1 = x4[j0 + 1];
        __half2 h0 = __floats2half2_rn(v0.x * c, v0.y * c);
        __half2 h1 = __floats2half2_rn(v0.z * c, v0.w * c);
        __half2 h2 = __floats2half2_rn(v1.x * c, v1.y * c);
        __half2 h3 = __floats2half2_rn(v1.z * c, v1.w * c);
        ((uint4*)g_xh)[i] = make_uint4(*(unsigned*)&h0, *(unsigned*)&h1,
                                       *(unsigned*)&h2, *(unsigned*)&h3);
    }
}

// ---------------- CSR bucket fill (2 edges/thread) ---------------------------
__global__ void k_fill(const int2* __restrict__ src2, const int2* __restrict__ dst2) {
    int i = blockIdx.x * blockDim.x + threadIdx.x;
    if (i < N_EDGES / 2) {
        int2 s = src2[i], d = dst2[i];
        int p0 = atomicAdd(&g_cursor[d.x], 1);
        g_csr[p0] = s.x;
        int p1 = atomicAdd(&g_cursor[d.y], 1);
        g_csr[p1] = s.y;
    }
}

// ---------------- fused layer-1: fp16 gather + W1 GEMM + relu + W2 -> y ------
// 384 threads (12 warps), warp handles 4 nodes, 48 nodes/block, 3 CTAs/SM.
__global__ void __launch_bounds__(TB_F1, 3) k_fused1(const float* __restrict__ W1,
                                                     const float* __restrict__ b1,
                                                     const float* __restrict__ W2) {
    extern __shared__ float smem[];
    float4* Ws   = (float4*)smem;                  // 4096 float4: W1[k][c]
    float4* b1s4 = (float4*)(smem + 16384);        // 32 float4
    float2* W2s  = (float2*)(smem + 16384 + 128);  // 128 float2

    int tid = threadIdx.x;
    const float4* W14 = (const float4*)W1;
    for (int i = tid; i < 4096; i += TB_F1) Ws[i] = W14[i];
    if (tid < 32)  b1s4[tid] = ((const float4*)b1)[tid];
    if (tid < 128) W2s[tid]  = ((const float2*)W2)[tid];
    __syncthreads();

    int warp = tid >> 5, lane = tid & 31;
    int i0 = blockIdx.x * 48 + warp * 4;           // up to 100028 on last block

    const uint2* xh2 = (const uint2*)g_xh;         // 8 B = 4 halves per lane

    float4 a[4];
    #pragma unroll
    for (int m = 0; m < 4; m++) {
        int node = i0 + m;
        float4 acc = make_float4(0.f, 0.f, 0.f, 0.f);
        if (node < N_NODES) {
            int beg = __ldg(&g_rowp[node]), end = __ldg(&g_rowp[node + 1]);
            int e = beg;
            for (; e + 4 <= end; e += 4) {
                int s0 = __ldg(&g_csr[e]),     s1 = __ldg(&g_csr[e + 1]);
                int s2 = __ldg(&g_csr[e + 2]), s3 = __ldg(&g_csr[e + 3]);
                uint2 v0 = xh2[s0 * 32 + lane];
                uint2 v1 = xh2[s1 * 32 + lane];
                uint2 v2 = xh2[s2 * 32 + lane];
                uint2 v3 = xh2[s3 * 32 + lane];
                float2 f;
                f = __half22float2(*(__half2*)&v0.x); acc.x += f.x; acc.y += f.y;
                f = __half22float2(*(__half2*)&v0.y); acc.z += f.x; acc.w += f.y;
                f = __half22float2(*(__half2*)&v1.x); acc.x += f.x; acc.y += f.y;
                f = __half22float2(*(__half2*)&v1.y); acc.z += f.x; acc.w += f.y;
                f = __half22float2(*(__half2*)&v2.x); acc.x += f.x; acc.y += f.y;
                f = __half22float2(*(__half2*)&v2.y); acc.z += f.x; acc.w += f.y;
                f = __half22float2(*(__half2*)&v3.x); acc.x += f.x; acc.y += f.y;
                f = __half22float2(*(__half2*)&v3.y); acc.z += f.x; acc.w += f.y;
            }
            for (; e < end; ++e) {
                int s0 = __ldg(&g_csr[e]);
                uint2 v0 = xh2[s0 * 32 + lane];
                float2 f;
                f = __half22float2(*(__half2*)&v0.x); acc.x += f.x; acc.y += f.y;
                f = __half22float2(*(__half2*)&v0.y); acc.z += f.x; acc.w += f.y;
            }
            float ri = g_rs_in[node];
            acc.x *= ri; acc.y *= ri; acc.z *= ri; acc.w *= ri;
        }
        a[m] = acc;
    }

    float4 acc[4];
    #pragma unroll
    for (int m = 0; m < 4; m++) acc[m] = b1s4[lane];

    #pragma unroll 8
    for (int sl = 0; sl < 32; ++sl) {
        #pragma unroll
        for (int j = 0; j < 4; j++) {
            int k = sl * 4 + j;
            float4 wv = Ws[k * 32 + lane];
            float x0, x1, x2, x3;
            if      (j == 0) { x0 = a[0].x; x1 = a[1].x; x2 = a[2].x; x3 = a[3].x; }
            else if (j == 1) { x0 = a[0].y; x1 = a[1].y; x2 = a[2].y; x3 = a[3].y; }
            else if (j == 2) { x0 = a[0].z; x1 = a[1].z; x2 = a[2].z; x3 = a[3].z; }
            else             { x0 = a[0].w; x1 = a[1].w; x2 = a[2].w; x3 = a[3].w; }
            x0 = __shfl_sync(0xffffffffu, x0, sl);
            x1 = __shfl_sync(0xffffffffu, x1, sl);
            x2 = __shfl_sync(0xffffffffu, x2, sl);
            x3 = __shfl_sync(0xffffffffu, x3, sl);
            acc[0].x += x0 * wv.x; acc[0].y += x0 * wv.y; acc[0].z += x0 * wv.z; acc[0].w += x0 * wv.w;
            acc[1].x += x1 * wv.x; acc[1].y += x1 * wv.y; acc[1].z += x1 * wv.z; acc[1].w += x1 * wv.w;
            acc[2].x += x2 * wv.x; acc[2].y += x2 * wv.y; acc[2].z += x2 * wv.z; acc[2].w += x2 * wv.w;
            acc[3].x += x3 * wv.x; acc[3].y += x3 * wv.y; acc[3].z += x3 * wv.z; acc[3].w += x3 * wv.w;
        }
    }

    float2 w0 = W2s[4 * lane + 0], w1 = W2s[4 * lane + 1];
    float2 w2 = W2s[4 * lane + 2], w3 = W2s[4 * lane + 3];
    float p0[4], p1[4];
    #pragma unroll
    for (int m = 0; m < 4; m++) {
        float h0 = fmaxf(acc[m].x, 0.f), h1 = fmaxf(acc[m].y, 0.f);
        float h2 = fmaxf(acc[m].z, 0.f), h3 = fmaxf(acc[m].w, 0.f);
        p0[m] = h0 * w0.x + h1 * w1.x + h2 * w2.x + h3 * w3.x;
        p1[m] = h0 * w0.y + h1 * w1.y + h2 * w2.y + h3 * w3.y;
    }
    #pragma unroll
    for (int off = 16; off; off >>= 1) {
        #pragma unroll
        for (int m = 0; m < 4; m++) {
            p0[m] += __shfl_xor_sync(0xffffffffu, p0[m], off);
            p1[m] += __shfl_xor_sync(0xffffffffu, p1[m], off);
        }
    }
    if (lane == 0) {
        float2* y2 = (float2*)g_y;
        #pragma unroll
        for (int m = 0; m < 4; m++) {
            int node = i0 + m;
            if (node < N_NODES) {
                float ro = g_rs_out[node];
                y2[node] = make_float2(p0[m] * ro, p1[m] * ro);
            }
        }
    }
}

// ---------------- layer-2: CSR gather of y + finalize ------------------------
__global__ void k_out(float* __restrict__ out, const float* __restrict__ b2) {
    int i = blockIdx.x * blockDim.x + threadIdx.x;
    if (i >= N_NODES) return;
    int beg = __ldg(&g_rowp[i]), end = __ldg(&g_rowp[i + 1]);
    const float2* y2 = (const float2*)g_y;
    float s0 = 0.f, s1 = 0.f;
    int e = beg;
    for (; e + 2 <= end; e += 2) {
        int a = __ldg(&g_csr[e]), b = __ldg(&g_csr[e + 1]);
        float2 va = y2[a], vb = y2[b];
        s0 += va.x + vb.x;
        s1 += va.y + vb.y;
    }
    if (e < end) {
        float2 va = y2[__ldg(&g_csr[e])];
        s0 += va.x; s1 += va.y;
    }
    float ri = g_rs_in[i];
    ((float2*)out)[i] = make_float2(s0 * ri + __ldg(&b2[0]),
                                    s1 * ri + __ldg(&b2[1]));
}

// ---------------- launch ------------------------------------------------------
extern "C" void kernel_launch(void* const* d_in, const int* in_sizes, int n_in,
                              void* d_out, int out_size) {
    const float* in_feat = (const float*)d_in[0];
    const int*   src     = (const int*)d_in[1];
    const int*   dst     = (const int*)d_in[2];
    const float* W1      = (const float*)d_in[3];
    const float* b1      = (const float*)d_in[4];
    const float* W2      = (const float*)d_in[5];
    const float* b2      = (const float*)d_in[6];
    float*       out     = (float*)d_out;

    const int T = 256;
    const int SMEM_NODE = (16384 + 128 + 256) * (int)sizeof(float); // 67072 B
    cudaFuncSetAttribute(k_fused1, cudaFuncAttributeMaxDynamicSharedMemorySize, SMEM_NODE);

    k_zero<<<(N_NODES + T - 1) / T, T>>>();
    k_deg<<<(N_EDGES / 2 + T - 1) / T, T>>>((const int2*)src, (const int2*)dst);
    k_scan_block<<<NB_SCAN, 1024>>>();
    k_tohalf<<<(N_NODES * 16 + T - 1) / T, T>>>((const float4*)in_feat);
    k_scan_fin<<<NB_SCAN, 1024>>>();
    k_fill<<<(N_EDGES / 2 + T - 1) / T, T>>>((const int2*)src, (const int2*)dst);
    k_fused1<<<NB_F1, TB_F1, SMEM_NODE>>>(W1, b1, W2);
    k_out<<<(N_NODES + T - 1) / T, T>>>(out, b2);
}

// round 10
// speedup vs baseline: 1.6662x; 1.3397x over previous
#include <cuda_runtime.h>
#include <cuda_fp16.h>
#include <mma.h>

#define N_NODES 100000
#define N_EDGES 1600000
#define F 128
#define NB_SCAN 98            // ceil(100000/1024)
#define TB_F1 384             // fused1 block size (12 warps, 48 nodes/block)
#define NB_F1 2084            // ceil(100000/48)

// smem layout (bytes) for k_fused1
#define SM_W1H  0             // __half [128][136] = 34816  (row-major [k][n])
#define SM_AT   34816         // __half [48][136]  = 13056  (row-major [node][k])
#define SM_H    47872         // float  [48][132]  = 25344
#define SM_B1   73216         // float  [128]      = 512
#define SM_W2   73728         // float  [256]      = 1024
#define SM_F1_TOTAL 74752

// ---------------- scratch (static __device__, no allocation) ----------------
__device__ int   g_deg_out_i[N_NODES];
__device__ int   g_deg_in_i[N_NODES];
__device__ float g_rs_out[N_NODES];
__device__ float g_rs_in[N_NODES];
__device__ int   g_rowp[N_NODES + 1];     // CSR row pointers (by dst)
__device__ int   g_cursor[N_NODES];       // fill cursors
__device__ int   g_csr[N_EDGES];          // src indices grouped by dst
__device__ int   g_bsum[NB_SCAN];
__device__ float g_y[(size_t)N_NODES * 2];
__device__ __align__(16) __half g_xh[(size_t)N_NODES * F];  // fp16(x * rs_out)

// ---------------- zero counters ----------------------------------------------
__global__ void k_zero() {
    int i = blockIdx.x * blockDim.x + threadIdx.x;
    if (i < N_NODES) { g_deg_out_i[i] = 0; g_deg_in_i[i] = 0; }
}

// ---------------- degrees (int histogram, 2 edges/thread) --------------------
__global__ void k_deg(const int2* __restrict__ src2, const int2* __restrict__ dst2) {
    int i = blockIdx.x * blockDim.x + threadIdx.x;
    if (i < N_EDGES / 2) {
        int2 s = src2[i], d = dst2[i];
        atomicAdd(&g_deg_out_i[s.x], 1);
        atomicAdd(&g_deg_out_i[s.y], 1);
        atomicAdd(&g_deg_in_i[d.x], 1);
        atomicAdd(&g_deg_in_i[d.y], 1);
    }
}

// ---------------- block scan of deg_in (warp-shuffle) + rs -------------------
__global__ void k_scan_block() {
    __shared__ int wsum[32];
    int tid = threadIdx.x, lane = tid & 31, wid = tid >> 5;
    int gid = blockIdx.x * 1024 + tid;
    int v = (gid < N_NODES) ? g_deg_in_i[gid] : 0;
    int x = v;
    #pragma unroll
    for (int off = 1; off < 32; off <<= 1) {
        int t = __shfl_up_sync(0xffffffffu, x, off);
        if (lane >= off) x += t;
    }
    if (lane == 31) wsum[wid] = x;
    __syncthreads();
    if (wid == 0) {
        int s = wsum[lane];
        #pragma unroll
        for (int off = 1; off < 32; off <<= 1) {
            int t = __shfl_up_sync(0xffffffffu, s, off);
            if (lane >= off) s += t;
        }
        wsum[lane] = s;
    }
    __syncthreads();
    int inc = x + (wid ? wsum[wid - 1] : 0);
    if (gid < N_NODES) {
        g_rowp[gid + 1] = inc;                         // inclusive, pre-offset
        g_rs_in[gid]  = rsqrtf(fmaxf((float)v, 1.0f));
        g_rs_out[gid] = rsqrtf(fmaxf((float)g_deg_out_i[gid], 1.0f));
    }
    if (tid == 1023) g_bsum[blockIdx.x] = inc;
}

// ---------------- finalize scan: per-block offset reduce + add-back ----------
__global__ void k_scan_fin() {                         // grid NB_SCAN, block 1024
    __shared__ int wred[32];
    __shared__ int s_off;
    int tid = threadIdx.x, lane = tid & 31, wid = tid >> 5;
    int bid = blockIdx.x;
    int v = (tid < bid) ? g_bsum[tid] : 0;             // bid <= 97 < 1024
    #pragma unroll
    for (int off = 16; off; off >>= 1) v += __shfl_xor_sync(0xffffffffu, v, off);
    if (lane == 0) wred[wid] = v;
    __syncthreads();
    if (wid == 0) {
        int t = wred[lane];
        #pragma unroll
        for (int off = 16; off; off >>= 1) t += __shfl_xor_sync(0xffffffffu, t, off);
        if (lane == 0) s_off = t;
    }
    __syncthreads();
    int off = s_off;
    int gid = bid * 1024 + tid;
    if (gid < N_NODES) {
        int val = g_rowp[gid + 1] + off;
        g_rowp[gid + 1] = val;
        if (gid + 1 < N_NODES) g_cursor[gid + 1] = val;
        if (gid == 0) { g_rowp[0] = 0; g_cursor[0] = 0; }
    }
}

// ---------------- x -> fp16(x * rs_out), vectorized --------------------------
__global__ void k_tohalf(const float4* __restrict__ x4) {
    int i = blockIdx.x * blockDim.x + threadIdx.x;
    if (i < N_NODES * 16) {
        int j0 = i * 2;
        float c = g_rs_out[j0 >> 5];
        float4 v0 = x4[j0], v1 = x4[j0 + 1];
        __half2 h0 = __floats2half2_rn(v0.x * c, v0.y * c);
        __half2 h1 = __floats2half2_rn(v0.z * c, v0.w * c);
        __half2 h2 = __floats2half2_rn(v1.x * c, v1.y * c);
        __half2 h3 = __floats2half2_rn(v1.z * c, v1.w * c);
        ((uint4*)g_xh)[i] = make_uint4(*(unsigned*)&h0, *(unsigned*)&h1,
                                       *(unsigned*)&h2, *(unsigned*)&h3);
    }
}

// ---------------- CSR bucket fill (2 edges/thread) ---------------------------
__global__ void k_fill(const int2* __restrict__ src2, const int2* __restrict__ dst2) {
    int i = blockIdx.x * blockDim.x + threadIdx.x;
    if (i < N_EDGES / 2) {
        int2 s = src2[i], d = dst2[i];
        int p0 = atomicAdd(&g_cursor[d.x], 1);
        g_csr[p0] = s.x;
        int p1 = atomicAdd(&g_cursor[d.y], 1);
        g_csr[p1] = s.y;
    }
}

// ---------------- fused layer-1: gather + wmma W1 GEMM + relu + W2 -> y ------
// 384 threads (12 warps). Warp gathers 4 nodes into fp16 A-tile; block computes
// H[48][128] = A @ W1 via 24 wmma 16x16x16 tiles (2/warp); epilogue adds b1,
// relu, projects through W2 (128x2) and scales by rs_out.
__global__ void __launch_bounds__(TB_F1, 3) k_fused1(const float* __restrict__ W1,
                                                     const float* __restrict__ b1,
                                                     const float* __restrict__ W2) {
    using namespace nvcuda;
    extern __shared__ char smraw[];
    __half* W1h = (__half*)(smraw + SM_W1H);   // [k=128][n=136 pad] row-major
    __half* At  = (__half*)(smraw + SM_AT);    // [node=48][k=136 pad] row-major
    float*  Hs  = (float*)(smraw + SM_H);      // [node=48][n=132 pad]
    float*  b1s = (float*)(smraw + SM_B1);     // [128]
    float*  W2s = (float*)(smraw + SM_W2);     // [256]

    int tid = threadIdx.x;
    // stage W1 as fp16 row-major [k][n] (no transpose)
    for (int idx = tid; idx < 16384; idx += TB_F1) {
        int k = idx >> 7, n = idx & 127;
        W1h[k * 136 + n] = __float2half_rn(W1[idx]);
    }
    if (tid < 128) b1s[tid] = b1[tid];
    if (tid < 256) W2s[tid] = W2[tid];

    int warp = tid >> 5, lane = tid & 31;
    int i0 = blockIdx.x * 48 + warp * 4;

    const uint2* xh2 = (const uint2*)g_xh;     // 4 halves per lane per edge

    // --- gather: 4 nodes/warp, lane owns feats 4l..4l+3, fp32 accum ---
    #pragma unroll
    for (int m = 0; m < 4; m++) {
        int node = i0 + m;
        float4 acc = make_float4(0.f, 0.f, 0.f, 0.f);
        if (node < N_NODES) {
            int beg = __ldg(&g_rowp[node]), end = __ldg(&g_rowp[node + 1]);
            int e = beg;
            for (; e + 4 <= end; e += 4) {
                int s0 = __ldg(&g_csr[e]),     s1 = __ldg(&g_csr[e + 1]);
                int s2 = __ldg(&g_csr[e + 2]), s3 = __ldg(&g_csr[e + 3]);
                uint2 v0 = xh2[s0 * 32 + lane];
                uint2 v1 = xh2[s1 * 32 + lane];
                uint2 v2 = xh2[s2 * 32 + lane];
                uint2 v3 = xh2[s3 * 32 + lane];
                float2 f;
                f = __half22float2(*(__half2*)&v0.x); acc.x += f.x; acc.y += f.y;
                f = __half22float2(*(__half2*)&v0.y); acc.z += f.x; acc.w += f.y;
                f = __half22float2(*(__half2*)&v1.x); acc.x += f.x; acc.y += f.y;
                f = __half22float2(*(__half2*)&v1.y); acc.z += f.x; acc.w += f.y;
                f = __half22float2(*(__half2*)&v2.x); acc.x += f.x; acc.y += f.y;
                f = __half22float2(*(__half2*)&v2.y); acc.z += f.x; acc.w += f.y;
                f = __half22float2(*(__half2*)&v3.x); acc.x += f.x; acc.y += f.y;
                f = __half22float2(*(__half2*)&v3.y); acc.z += f.x; acc.w += f.y;
            }
            for (; e < end; ++e) {
                int s0 = __ldg(&g_csr[e]);
                uint2 v0 = xh2[s0 * 32 + lane];
                float2 f;
                f = __half22float2(*(__half2*)&v0.x); acc.x += f.x; acc.y += f.y;
                f = __half22float2(*(__half2*)&v0.y); acc.z += f.x; acc.w += f.y;
            }
            float ri = g_rs_in[node];
            acc.x *= ri; acc.y *= ri; acc.z *= ri; acc.w *= ri;
        }
        __half2 h01 = __floats2half2_rn(acc.x, acc.y);
        __half2 h23 = __floats2half2_rn(acc.z, acc.w);
        *(uint2*)(At + (warp * 4 + m) * 136 + 4 * lane) =
            make_uint2(*(unsigned*)&h01, *(unsigned*)&h23);
    }
    __syncthreads();   // A tile + W1h ready

    // --- wmma: H = A(48x128) @ W1(128x128), 24 tiles, 2 per warp ---
    {
        wmma::fragment<wmma::matrix_a, 16, 16, 16, __half, wmma::row_major> af;
        wmma::fragment<wmma::matrix_b, 16, 16, 16, __half, wmma::row_major> bf;
        wmma::fragment<wmma::accumulator, 16, 16, 16, float> cf;
        #pragma unroll
        for (int t = warp; t < 24; t += 12) {
            int mi = t >> 3, ni = t & 7;
            wmma::fill_fragment(cf, 0.0f);
            #pragma unroll
            for (int k0 = 0; k0 < 8; k0++) {
                wmma::load_matrix_sync(af, At + (mi * 16) * 136 + k0 * 16, 136);
                wmma::load_matrix_sync(bf, W1h + (k0 * 16) * 136 + ni * 16, 136);
                wmma::mma_sync(cf, af, bf, cf);
            }
            wmma::store_matrix_sync(Hs + (mi * 16) * 132 + ni * 16, cf, 132,
                                    wmma::mem_row_major);
        }
    }
    __syncthreads();   // H ready

    // --- epilogue: h = relu(H + b1); p = h @ W2; warp-reduce; *rs_out -> y ---
    float4 bb = ((const float4*)b1s)[lane];
    float2 w0 = ((float2*)W2s)[4 * lane + 0], w1 = ((float2*)W2s)[4 * lane + 1];
    float2 w2 = ((float2*)W2s)[4 * lane + 2], w3 = ((float2*)W2s)[4 * lane + 3];
    float p0[4], p1[4];
    #pragma unroll
    for (int m = 0; m < 4; m++) {
        float4 h = *(float4*)(Hs + (warp * 4 + m) * 132 + 4 * lane);
        float h0 = fmaxf(h.x + bb.x, 0.f), h1 = fmaxf(h.y + bb.y, 0.f);
        float h2 = fmaxf(h.z + bb.z, 0.f), h3 = fmaxf(h.w + bb.w, 0.f);
        p0[m] = h0 * w0.x + h1 * w1.x + h2 * w2.x + h3 * w3.x;
        p1[m] = h0 * w0.y + h1 * w1.y + h2 * w2.y + h3 * w3.y;
    }
    #pragma unroll
    for (int off = 16; off; off >>= 1) {
        #pragma unroll
        for (int m = 0; m < 4; m++) {
            p0[m] += __shfl_xor_sync(0xffffffffu, p0[m], off);
            p1[m] += __shfl_xor_sync(0xffffffffu, p1[m], off);
        }
    }
    if (lane == 0) {
        float2* y2 = (float2*)g_y;
        #pragma unroll
        for (int m = 0; m < 4; m++) {
            int node = i0 + m;
            if (node < N_NODES) {
                float ro = g_rs_out[node];
                y2[node] = make_float2(p0[m] * ro, p1[m] * ro);
            }
        }
    }
}

// ---------------- layer-2: CSR gather of y + finalize ------------------------
__global__ void k_out(float* __restrict__ out, const float* __restrict__ b2) {
    int i = blockIdx.x * blockDim.x + threadIdx.x;
    if (i >= N_NODES) return;
    int beg = __ldg(&g_rowp[i]), end = __ldg(&g_rowp[i + 1]);
    const float2* y2 = (const float2*)g_y;
    float s0 = 0.f, s1 = 0.f;
    int e = beg;
    for (; e + 2 <= end; e += 2) {
        int a = __ldg(&g_csr[e]), b = __ldg(&g_csr[e + 1]);
        float2 va = y2[a], vb = y2[b];
        s0 += va.x + vb.x;
        s1 += va.y + vb.y;
    }
    if (e < end) {
        float2 va = y2[__ldg(&g_csr[e])];
        s0 += va.x; s1 += va.y;
    }
    float ri = g_rs_in[i];
    ((float2*)out)[i] = make_float2(s0 * ri + __ldg(&b2[0]),
                                    s1 * ri + __ldg(&b2[1]));
}

// ---------------- launch ------------------------------------------------------
extern "C" void kernel_launch(void* const* d_in, const int* in_sizes, int n_in,
                              void* d_out, int out_size) {
    const float* in_feat = (const float*)d_in[0];
    const int*   src     = (const int*)d_in[1];
    const int*   dst     = (const int*)d_in[2];
    const float* W1      = (const float*)d_in[3];
    const float* b1      = (const float*)d_in[4];
    const float* W2      = (const float*)d_in[5];
    const float* b2      = (const float*)d_in[6];
    float*       out     = (float*)d_out;

    const int T = 256;
    cudaFuncSetAttribute(k_fused1, cudaFuncAttributeMaxDynamicSharedMemorySize, SM_F1_TOTAL);

    k_zero<<<(N_NODES + T - 1) / T, T>>>();
    k_deg<<<(N_EDGES / 2 + T - 1) / T, T>>>((const int2*)src, (const int2*)dst);
    k_scan_block<<<NB_SCAN, 1024>>>();
    k_tohalf<<<(N_NODES * 16 + T - 1) / T, T>>>((const float4*)in_feat);
    k_scan_fin<<<NB_SCAN, 1024>>>();
    k_fill<<<(N_EDGES / 2 + T - 1) / T, T>>>((const int2*)src, (const int2*)dst);
    k_fused1<<<NB_F1, TB_F1, SM_F1_TOTAL>>>(W1, b1, W2);
    k_out<<<(N_NODES + T - 1) / T, T>>>(out, b2);
}

// round 13
// speedup vs baseline: 1.7537x; 1.0525x over previous
#include <cuda_runtime.h>
#include <cuda_fp16.h>
#include <mma.h>

#define N_NODES 100000
#define N_EDGES 1600000
#define F 128
#define NB_SCAN 98            // ceil(100000/1024)
#define TB_F1 384             // fused1 block size (12 warps, 48 nodes/block)
#define NB_F1 2084            // ceil(100000/48)

// smem layout (bytes) for k_fused1
#define SM_W1H  0             // __half [128][136] = 34816  (row-major [k][n])
#define SM_AT   34816         // __half [48][136]  = 13056  (row-major [node][k])
#define SM_H    47872         // float  [48][132]  = 25344
#define SM_B1   73216         // float  [128]      = 512
#define SM_W2   73728         // float  [256]      = 1024
#define SM_F1_TOTAL 74752

// ---------------- scratch (static __device__, no allocation) ----------------
__device__ int   g_deg_out_i[N_NODES];
__device__ int   g_deg_in_i[N_NODES];
__device__ float g_rs_out[N_NODES];
__device__ float g_rs_in[N_NODES];
__device__ int   g_rowp[N_NODES + 1];     // CSR row pointers (by dst)
__device__ int   g_cursor[N_NODES];       // fill cursors
__device__ int   g_csr[N_EDGES];          // src indices grouped by dst
__device__ int   g_bsum[NB_SCAN];
__device__ float g_y[(size_t)N_NODES * 2];
__device__ __align__(16) __half g_xh[(size_t)N_NODES * F];  // fp16(x * rs_out)
__device__ __align__(16) __half g_w1h[F * F];               // fp16(W1), [k][n]

// ---------------- zero counters + W1 -> fp16 ---------------------------------
__global__ void k_zero(const float* __restrict__ W1) {
    int i = blockIdx.x * blockDim.x + threadIdx.x;
    if (i < N_NODES) { g_deg_out_i[i] = 0; g_deg_in_i[i] = 0; }
    if (i < F * F / 2) {                       // 8192 float2 -> half2
        float2 v = ((const float2*)W1)[i];
        ((__half2*)g_w1h)[i] = __floats2half2_rn(v.x, v.y);
    }
}

// ---------------- degrees (int histogram, 4 edges/thread) --------------------
__global__ void k_deg(const int4* __restrict__ src4, const int4* __restrict__ dst4) {
    int i = blockIdx.x * blockDim.x + threadIdx.x;
    if (i < N_EDGES / 4) {
        int4 s = src4[i], d = dst4[i];
        atomicAdd(&g_deg_out_i[s.x], 1);
        atomicAdd(&g_deg_out_i[s.y], 1);
        atomicAdd(&g_deg_out_i[s.z], 1);
        atomicAdd(&g_deg_out_i[s.w], 1);
        atomicAdd(&g_deg_in_i[d.x], 1);
        atomicAdd(&g_deg_in_i[d.y], 1);
        atomicAdd(&g_deg_in_i[d.z], 1);
        atomicAdd(&g_deg_in_i[d.w], 1);
    }
}

// ---------------- block scan of deg_in (warp-shuffle) + rs -------------------
__global__ void k_scan_block() {
    __shared__ int wsum[32];
    int tid = threadIdx.x, lane = tid & 31, wid = tid >> 5;
    int gid = blockIdx.x * 1024 + tid;
    int v = (gid < N_NODES) ? g_deg_in_i[gid] : 0;
    int x = v;
    #pragma unroll
    for (int off = 1; off < 32; off <<= 1) {
        int t = __shfl_up_sync(0xffffffffu, x, off);
        if (lane >= off) x += t;
    }
    if (lane == 31) wsum[wid] = x;
    __syncthreads();
    if (wid == 0) {
        int s = wsum[lane];
        #pragma unroll
        for (int off = 1; off < 32; off <<= 1) {
            int t = __shfl_up_sync(0xffffffffu, s, off);
            if (lane >= off) s += t;
        }
        wsum[lane] = s;
    }
    __syncthreads();
    int inc = x + (wid ? wsum[wid - 1] : 0);
    if (gid < N_NODES) {
        g_rowp[gid + 1] = inc;                         // inclusive, pre-offset
        g_rs_in[gid]  = rsqrtf(fmaxf((float)v, 1.0f));
        g_rs_out[gid] = rsqrtf(fmaxf((float)g_deg_out_i[gid], 1.0f));
    }
    if (tid == 1023) g_bsum[blockIdx.x] = inc;
}

// ---------------- finalize scan: per-block offset reduce + add-back ----------
__global__ void k_scan_fin() {                         // grid NB_SCAN, block 1024
    __shared__ int wred[32];
    __shared__ int s_off;
    int tid = threadIdx.x, lane = tid & 31, wid = tid >> 5;
    int bid = blockIdx.x;
    int v = (tid < bid) ? g_bsum[tid] : 0;             // bid <= 97 < 1024
    #pragma unroll
    for (int off = 16; off; off >>= 1) v += __shfl_xor_sync(0xffffffffu, v, off);
    if (lane == 0) wred[wid] = v;
    __syncthreads();
    if (wid == 0) {
        int t = wred[lane];
        #pragma unroll
        for (int off = 16; off; off >>= 1) t += __shfl_xor_sync(0xffffffffu, t, off);
        if (lane == 0) s_off = t;
    }
    __syncthreads();
    int off = s_off;
    int gid = bid * 1024 + tid;
    if (gid < N_NODES) {
        int val = g_rowp[gid + 1] + off;
        g_rowp[gid + 1] = val;
        if (gid + 1 < N_NODES) g_cursor[gid + 1] = val;
        if (gid == 0) { g_rowp[0] = 0; g_cursor[0] = 0; }
    }
}

// ---------------- x -> fp16(x * rs_out), vectorized --------------------------
__global__ void k_tohalf(const float4* __restrict__ x4) {
    int i = blockIdx.x * blockDim.x + threadIdx.x;
    if (i < N_NODES * 16) {
        int j0 = i * 2;
        float c = g_rs_out[j0 >> 5];
        float4 v0 = x4[j0], v1 = x4[j0 + 1];
        __half2 h0 = __floats2half2_rn(v0.x * c, v0.y * c);
        __half2 h1 = __floats2half2_rn(v0.z * c, v0.w * c);
        __half2 h2 = __floats2half2_rn(v1.x * c, v1.y * c);
        __half2 h3 = __floats2half2_rn(v1.z * c, v1.w * c);
        ((uint4*)g_xh)[i] = make_uint4(*(unsigned*)&h0, *(unsigned*)&h1,
                                       *(unsigned*)&h2, *(unsigned*)&h3);
    }
}

// ---------------- CSR bucket fill (4 edges/thread) ---------------------------
__global__ void k_fill(const int4* __restrict__ src4, const int4* __restrict__ dst4) {
    int i = blockIdx.x * blockDim.x + threadIdx.x;
    if (i < N_EDGES / 4) {
        int4 s = src4[i], d = dst4[i];
        int p0 = atomicAdd(&g_cursor[d.x], 1); g_csr[p0] = s.x;
        int p1 = atomicAdd(&g_cursor[d.y], 1); g_csr[p1] = s.y;
        int p2 = atomicAdd(&g_cursor[d.z], 1); g_csr[p2] = s.z;
        int p3 = atomicAdd(&g_cursor[d.w], 1); g_csr[p3] = s.w;
    }
}

// ---------------- fused layer-1: gather + wmma W1 GEMM + relu + W2 -> y ------
__global__ void __launch_bounds__(TB_F1, 3) k_fused1(const float* __restrict__ b1,
                                                     const float* __restrict__ W2) {
    using namespace nvcuda;
    extern __shared__ char smraw[];
    __half* W1h = (__half*)(smraw + SM_W1H);   // [k=128][n=136 pad] row-major
    __half* At  = (__half*)(smraw + SM_AT);    // [node=48][k=136 pad] row-major
    float*  Hs  = (float*)(smraw + SM_H);      // [node=48][n=132 pad]
    float*  b1s = (float*)(smraw + SM_B1);     // [128]
    float*  W2s = (float*)(smraw + SM_W2);     // [256]

    int tid = threadIdx.x;
    // stage fp16 W1 from global (2048 uint4 = 16384 halves), keep [k][n] + pad
    for (int idx = tid; idx < 2048; idx += TB_F1) {
        int k = idx >> 4, n8 = idx & 15;       // 16 uint4 per 128-wide row
        *(uint4*)(W1h + k * 136 + n8 * 8) = ((const uint4*)g_w1h)[idx];
    }
    if (tid < 128) b1s[tid] = b1[tid];
    if (tid < 256) W2s[tid] = W2[tid];

    int warp = tid >> 5, lane = tid & 31;
    int i0 = blockIdx.x * 48 + warp * 4;

    const uint2* xh2 = (const uint2*)g_xh;     // 4 halves per lane per edge

    // --- gather: 4 nodes/warp, lane owns feats 4l..4l+3, dual fp32 chains ---
    #pragma unroll
    for (int m = 0; m < 4; m++) {
        int node = i0 + m;
        float4 accA = make_float4(0.f, 0.f, 0.f, 0.f);
        float4 accB = make_float4(0.f, 0.f, 0.f, 0.f);
        if (node < N_NODES) {
            int beg = __ldg(&g_rowp[node]), end = __ldg(&g_rowp[node + 1]);
            int e = beg;
            for (; e + 4 <= end; e += 4) {
                int s0 = __ldg(&g_csr[e]),     s1 = __ldg(&g_csr[e + 1]);
                int s2 = __ldg(&g_csr[e + 2]), s3 = __ldg(&g_csr[e + 3]);
                uint2 v0 = xh2[s0 * 32 + lane];
                uint2 v1 = xh2[s1 * 32 + lane];
                uint2 v2 = xh2[s2 * 32 + lane];
                uint2 v3 = xh2[s3 * 32 + lane];
                float2 f;
                f = __half22float2(*(__half2*)&v0.x); accA.x += f.x; accA.y += f.y;
                f = __half22float2(*(__half2*)&v0.y); accA.z += f.x; accA.w += f.y;
                f = __half22float2(*(__half2*)&v1.x); accB.x += f.x; accB.y += f.y;
                f = __half22float2(*(__half2*)&v1.y); accB.z += f.x; accB.w += f.y;
                f = __half22float2(*(__half2*)&v2.x); accA.x += f.x; accA.y += f.y;
                f = __half22float2(*(__half2*)&v2.y); accA.z += f.x; accA.w += f.y;
                f = __half22float2(*(__half2*)&v3.x); accB.x += f.x; accB.y += f.y;
                f = __half22float2(*(__half2*)&v3.y); accB.z += f.x; accB.w += f.y;
            }
            for (; e < end; ++e) {
                int s0 = __ldg(&g_csr[e]);
                uint2 v0 = xh2[s0 * 32 + lane];
                float2 f;
                f = __half22float2(*(__half2*)&v0.x); accA.x += f.x; accA.y += f.y;
                f = __half22float2(*(__half2*)&v0.y); accA.z += f.x; accA.w += f.y;
            }
            float ri = g_rs_in[node];
            accA.x = (accA.x + accB.x) * ri;
            accA.y = (accA.y + accB.y) * ri;
            accA.z = (accA.z + accB.z) * ri;
            accA.w = (accA.w + accB.w) * ri;
        }
        __half2 h01 = __floats2half2_rn(accA.x, accA.y);
        __half2 h23 = __floats2half2_rn(accA.z, accA.w);
        *(uint2*)(At + (warp * 4 + m) * 136 + 4 * lane) =
            make_uint2(*(unsigned*)&h01, *(unsigned*)&h23);
    }
    __syncthreads();   // A tile + W1h ready

    // --- wmma: H = A(48x128) @ W1(128x128), 24 tiles, 2 per warp ---
    {
        wmma::fragment<wmma::matrix_a, 16, 16, 16, __half, wmma::row_major> af;
        wmma::fragment<wmma::matrix_b, 16, 16, 16, __half, wmma::row_major> bf;
        wmma::fragment<wmma::accumulator, 16, 16, 16, float> cf;
        #pragma unroll
        for (int t = warp; t < 24; t += 12) {
            int mi = t >> 3, ni = t & 7;
            wmma::fill_fragment(cf, 0.0f);
            #pragma unroll
            for (int k0 = 0; k0 < 8; k0++) {
                wmma::load_matrix_sync(af, At + (mi * 16) * 136 + k0 * 16, 136);
                wmma::load_matrix_sync(bf, W1h + (k0 * 16) * 136 + ni * 16, 136);
                wmma::mma_sync(cf, af, bf, cf);
            }
            wmma::store_matrix_sync(Hs + (mi * 16) * 132 + ni * 16, cf, 132,
                                    wmma::mem_row_major);
        }
    }
    __syncthreads();   // H ready

    // --- epilogue: h = relu(H + b1); p = h @ W2; warp-reduce; *rs_out -> y ---
    float4 bb = ((const float4*)b1s)[lane];
    float2 w0 = ((float2*)W2s)[4 * lane + 0], w1 = ((float2*)W2s)[4 * lane + 1];
    float2 w2 = ((float2*)W2s)[4 * lane + 2], w3 = ((float2*)W2s)[4 * lane + 3];
    float p0[4], p1[4];
    #pragma unroll
    for (int m = 0; m < 4; m++) {
        float4 h = *(float4*)(Hs + (warp * 4 + m) * 132 + 4 * lane);
        float h0 = fmaxf(h.x + bb.x, 0.f), h1 = fmaxf(h.y + bb.y, 0.f);
        float h2 = fmaxf(h.z + bb.z, 0.f), h3 = fmaxf(h.w + bb.w, 0.f);
        p0[m] = h0 * w0.x + h1 * w1.x + h2 * w2.x + h3 * w3.x;
        p1[m] = h0 * w0.y + h1 * w1.y + h2 * w2.y + h3 * w3.y;
    }
    #pragma unroll
    for (int off = 16; off; off >>= 1) {
        #pragma unroll
        for (int m = 0; m < 4; m++) {
            p0[m] += __shfl_xor_sync(0xffffffffu, p0[m], off);
            p1[m] += __shfl_xor_sync(0xffffffffu, p1[m], off);
        }
    }
    if (lane == 0) {
        float2* y2 = (float2*)g_y;
        #pragma unroll
        for (int m = 0; m < 4; m++) {
            int node = i0 + m;
            if (node < N_NODES) {
                float ro = g_rs_out[node];
                y2[node] = make_float2(p0[m] * ro, p1[m] * ro);
            }
        }
    }
}

// ---------------- layer-2: CSR gather of y + finalize ------------------------
__global__ void k_out(float* __restrict__ out, const float* __restrict__ b2) {
    int i = blockIdx.x * blockDim.x + threadIdx.x;
    if (i >= N_NODES) return;
    int beg = __ldg(&g_rowp[i]), end = __ldg(&g_rowp[i + 1]);
    const float2* y2 = (const float2*)g_y;
    float s0 = 0.f, s1 = 0.f;
    int e = beg;
    for (; e + 2 <= end; e += 2) {
        int a = __ldg(&g_csr[e]), b = __ldg(&g_csr[e + 1]);
        float2 va = y2[a], vb = y2[b];
        s0 += va.x + vb.x;
        s1 += va.y + vb.y;
    }
    if (e < end) {
        float2 va = y2[__ldg(&g_csr[e])];
        s0 += va.x; s1 += va.y;
    }
    float ri = g_rs_in[i];
    ((float2*)out)[i] = make_float2(s0 * ri + __ldg(&b2[0]),
                                    s1 * ri + __ldg(&b2[1]));
}

// ---------------- launch ------------------------------------------------------
extern "C" void kernel_launch(void* const* d_in, const int* in_sizes, int n_in,
                              void* d_out, int out_size) {
    const float* in_feat = (const float*)d_in[0];
    const int*   src     = (const int*)d_in[1];
    const int*   dst     = (const int*)d_in[2];
    const float* W1      = (const float*)d_in[3];
    const float* b1      = (const float*)d_in[4];
    const float* W2      = (const float*)d_in[5];
    const float* b2      = (const float*)d_in[6];
    float*       out     = (float*)d_out;

    const int T = 256;
    cudaFuncSetAttribute(k_fused1, cudaFuncAttributeMaxDynamicSharedMemorySize, SM_F1_TOTAL);

    k_zero<<<(N_NODES + T - 1) / T, T>>>(W1);
    k_deg<<<(N_EDGES / 4 + T - 1) / T, T>>>((const int4*)src, (const int4*)dst);
    k_scan_block<<<NB_SCAN, 1024>>>();
    k_tohalf<<<(N_NODES * 16 + T - 1) / T, T>>>((const float4*)in_feat);
    k_scan_fin<<<NB_SCAN, 1024>>>();
    k_fill<<<(N_EDGES / 4 + T - 1) / T, T>>>((const int4*)src, (const int4*)dst);
    k_fused1<<<NB_F1, TB_F1, SM_F1_TOTAL>>>(b1, W2);
    k_out<<<(N_NODES + T - 1) / T, T>>>(out, b2);
}

// round 14
// speedup vs baseline: 1.7976x; 1.0250x over previous
#include <cuda_runtime.h>
#include <cuda_fp16.h>
#include <mma.h>

#define N_NODES 100000
#define N_EDGES 1600000
#define F 128
#define NB_SCAN 98            // ceil(100000/1024)
#define TB_F1 384             // fused1 block size (12 warps, 48 nodes/block)
#define NB_F1 2084            // ceil(100000/48)

#define NB_FILL   1563        // ceil(N_EDGES/4 / 256)
#define NB_TOHALF 6250        // N_NODES*16 / 256
#define NB_PREP   (NB_FILL + NB_TOHALF)

// smem layout (bytes) for k_fused1
#define SM_W1H  0             // __half [128][136] = 34816  (row-major [k][n])
#define SM_AT   34816         // __half [48][136]  = 13056  (row-major [node][k])
#define SM_H    47872         // float  [48][132]  = 25344
#define SM_B1   73216         // float  [128]      = 512
#define SM_W2   73728         // float  [256]      = 1024
#define SM_F1_TOTAL 74752

// ---------------- scratch (static __device__, no allocation) ----------------
__device__ int   g_deg_out_i[N_NODES];
__device__ int   g_deg_in_i[N_NODES];
__device__ float g_rs_out[N_NODES];
__device__ float g_rs_in[N_NODES];
__device__ int   g_rowp[N_NODES + 1];     // CSR row pointers (by dst)
__device__ int   g_cursor[N_NODES];       // fill cursors
__device__ int   g_csr[N_EDGES];          // src indices grouped by dst
__device__ int   g_bsum[NB_SCAN];
__device__ float g_y[(size_t)N_NODES * 2];
__device__ __align__(16) __half g_xh[(size_t)N_NODES * F];  // fp16(x * rs_out)
__device__ __align__(16) __half g_w1h[F * F];               // fp16(W1), [k][n]

// ---------------- zero counters + W1 -> fp16 ---------------------------------
__global__ void k_zero(const float* __restrict__ W1) {
    int i = blockIdx.x * blockDim.x + threadIdx.x;
    if (i < N_NODES) { g_deg_out_i[i] = 0; g_deg_in_i[i] = 0; }
    if (i < F * F / 2) {                       // 8192 float2 -> half2
        float2 v = ((const float2*)W1)[i];
        ((__half2*)g_w1h)[i] = __floats2half2_rn(v.x, v.y);
    }
}

// ---------------- degrees (int histogram, 4 edges/thread) --------------------
__global__ void k_deg(const int4* __restrict__ src4, const int4* __restrict__ dst4) {
    int i = blockIdx.x * blockDim.x + threadIdx.x;
    if (i < N_EDGES / 4) {
        int4 s = src4[i], d = dst4[i];
        atomicAdd(&g_deg_out_i[s.x], 1);
        atomicAdd(&g_deg_out_i[s.y], 1);
        atomicAdd(&g_deg_out_i[s.z], 1);
        atomicAdd(&g_deg_out_i[s.w], 1);
        atomicAdd(&g_deg_in_i[d.x], 1);
        atomicAdd(&g_deg_in_i[d.y], 1);
        atomicAdd(&g_deg_in_i[d.z], 1);
        atomicAdd(&g_deg_in_i[d.w], 1);
    }
}

// ---------------- block scan of deg_in (warp-shuffle) + rs -------------------
__global__ void k_scan_block() {
    __shared__ int wsum[32];
    int tid = threadIdx.x, lane = tid & 31, wid = tid >> 5;
    int gid = blockIdx.x * 1024 + tid;
    int v = (gid < N_NODES) ? g_deg_in_i[gid] : 0;
    int x = v;
    #pragma unroll
    for (int off = 1; off < 32; off <<= 1) {
        int t = __shfl_up_sync(0xffffffffu, x, off);
        if (lane >= off) x += t;
    }
    if (lane == 31) wsum[wid] = x;
    __syncthreads();
    if (wid == 0) {
        int s = wsum[lane];
        #pragma unroll
        for (int off = 1; off < 32; off <<= 1) {
            int t = __shfl_up_sync(0xffffffffu, s, off);
            if (lane >= off) s += t;
        }
        wsum[lane] = s;
    }
    __syncthreads();
    int inc = x + (wid ? wsum[wid - 1] : 0);
    if (gid < N_NODES) {
        g_rowp[gid + 1] = inc;                         // inclusive, pre-offset
        g_rs_in[gid]  = rsqrtf(fmaxf((float)v, 1.0f));
        g_rs_out[gid] = rsqrtf(fmaxf((float)g_deg_out_i[gid], 1.0f));
    }
    if (tid == 1023) g_bsum[blockIdx.x] = inc;
}

// ---------------- finalize scan: per-block offset reduce + add-back ----------
__global__ void k_scan_fin() {                         // grid NB_SCAN, block 1024
    __shared__ int wred[32];
    __shared__ int s_off;
    int tid = threadIdx.x, lane = tid & 31, wid = tid >> 5;
    int bid = blockIdx.x;
    int v = (tid < bid) ? g_bsum[tid] : 0;             // bid <= 97 < 1024
    #pragma unroll
    for (int off = 16; off; off >>= 1) v += __shfl_xor_sync(0xffffffffu, v, off);
    if (lane == 0) wred[wid] = v;
    __syncthreads();
    if (wid == 0) {
        int t = wred[lane];
        #pragma unroll
        for (int off = 16; off; off >>= 1) t += __shfl_xor_sync(0xffffffffu, t, off);
        if (lane == 0) s_off = t;
    }
    __syncthreads();
    int off = s_off;
    int gid = bid * 1024 + tid;
    if (gid < N_NODES) {
        int val = g_rowp[gid + 1] + off;
        g_rowp[gid + 1] = val;
        if (gid + 1 < N_NODES) g_cursor[gid + 1] = val;
        if (gid == 0) { g_rowp[0] = 0; g_cursor[0] = 0; }
    }
}

// ---------------- fused prep: CSR fill (blocks [0,NB_FILL)) +  ---------------
// ----------------             x->fp16 (blocks [NB_FILL,NB_PREP)) -------------
// Both depend only on k_scan_fin; resource-complementary (L2-atomic vs DRAM),
// so grid-partitioned fusion overlaps them without any stream API.
__global__ void __launch_bounds__(256) k_prep(const float4* __restrict__ x4,
                                              const int4* __restrict__ src4,
                                              const int4* __restrict__ dst4) {
    int b = blockIdx.x;
    if (b < NB_FILL) {
        int i = b * 256 + threadIdx.x;
        if (i < N_EDGES / 4) {
            int4 s = src4[i], d = dst4[i];
            int p0 = atomicAdd(&g_cursor[d.x], 1); g_csr[p0] = s.x;
            int p1 = atomicAdd(&g_cursor[d.y], 1); g_csr[p1] = s.y;
            int p2 = atomicAdd(&g_cursor[d.z], 1); g_csr[p2] = s.z;
            int p3 = atomicAdd(&g_cursor[d.w], 1); g_csr[p3] = s.w;
        }
    } else {
        int i = (b - NB_FILL) * 256 + threadIdx.x;   // < N_NODES*16 exactly
        int j0 = i * 2;
        float c = g_rs_out[j0 >> 5];
        float4 v0 = x4[j0], v1 = x4[j0 + 1];
        __half2 h0 = __floats2half2_rn(v0.x * c, v0.y * c);
        __half2 h1 = __floats2half2_rn(v0.z * c, v0.w * c);
        __half2 h2 = __floats2half2_rn(v1.x * c, v1.y * c);
        __half2 h3 = __floats2half2_rn(v1.z * c, v1.w * c);
        ((uint4*)g_xh)[i] = make_uint4(*(unsigned*)&h0, *(unsigned*)&h1,
                                       *(unsigned*)&h2, *(unsigned*)&h3);
    }
}

// ---------------- fused layer-1: gather + wmma W1 GEMM + relu + W2 -> y ------
__global__ void __launch_bounds__(TB_F1, 3) k_fused1(const float* __restrict__ b1,
                                                     const float* __restrict__ W2) {
    using namespace nvcuda;
    extern __shared__ char smraw[];
    __half* W1h = (__half*)(smraw + SM_W1H);   // [k=128][n=136 pad] row-major
    __half* At  = (__half*)(smraw + SM_AT);    // [node=48][k=136 pad] row-major
    float*  Hs  = (float*)(smraw + SM_H);      // [node=48][n=132 pad]
    float*  b1s = (float*)(smraw + SM_B1);     // [128]
    float*  W2s = (float*)(smraw + SM_W2);     // [256]

    int tid = threadIdx.x;
    // stage fp16 W1 from global (2048 uint4 = 16384 halves), keep [k][n] + pad
    for (int idx = tid; idx < 2048; idx += TB_F1) {
        int k = idx >> 4, n8 = idx & 15;       // 16 uint4 per 128-wide row
        *(uint4*)(W1h + k * 136 + n8 * 8) = ((const uint4*)g_w1h)[idx];
    }
    if (tid < 128) b1s[tid] = b1[tid];
    if (tid < 256) W2s[tid] = W2[tid];

    int warp = tid >> 5, lane = tid & 31;
    int i0 = blockIdx.x * 48 + warp * 4;

    const uint2* xh2 = (const uint2*)g_xh;     // 4 halves per lane per edge

    // --- gather: 4 nodes/warp, lane owns feats 4l..4l+3, dual fp32 chains ---
    #pragma unroll
    for (int m = 0; m < 4; m++) {
        int node = i0 + m;
        float4 accA = make_float4(0.f, 0.f, 0.f, 0.f);
        float4 accB = make_float4(0.f, 0.f, 0.f, 0.f);
        if (node < N_NODES) {
            int beg = __ldg(&g_rowp[node]), end = __ldg(&g_rowp[node + 1]);
            int e = beg;
            for (; e + 4 <= end; e += 4) {
                int s0 = __ldg(&g_csr[e]),     s1 = __ldg(&g_csr[e + 1]);
                int s2 = __ldg(&g_csr[e + 2]), s3 = __ldg(&g_csr[e + 3]);
                uint2 v0 = xh2[s0 * 32 + lane];
                uint2 v1 = xh2[s1 * 32 + lane];
                uint2 v2 = xh2[s2 * 32 + lane];
                uint2 v3 = xh2[s3 * 32 + lane];
                float2 f;
                f = __half22float2(*(__half2*)&v0.x); accA.x += f.x; accA.y += f.y;
                f = __half22float2(*(__half2*)&v0.y); accA.z += f.x; accA.w += f.y;
                f = __half22float2(*(__half2*)&v1.x); accB.x += f.x; accB.y += f.y;
                f = __half22float2(*(__half2*)&v1.y); accB.z += f.x; accB.w += f.y;
                f = __half22float2(*(__half2*)&v2.x); accA.x += f.x; accA.y += f.y;
                f = __half22float2(*(__half2*)&v2.y); accA.z += f.x; accA.w += f.y;
                f = __half22float2(*(__half2*)&v3.x); accB.x += f.x; accB.y += f.y;
                f = __half22float2(*(__half2*)&v3.y); accB.z += f.x; accB.w += f.y;
            }
            for (; e < end; ++e) {
                int s0 = __ldg(&g_csr[e]);
                uint2 v0 = xh2[s0 * 32 + lane];
                float2 f;
                f = __half22float2(*(__half2*)&v0.x); accA.x += f.x; accA.y += f.y;
                f = __half22float2(*(__half2*)&v0.y); accA.z += f.x; accA.w += f.y;
            }
            float ri = g_rs_in[node];
            accA.x = (accA.x + accB.x) * ri;
            accA.y = (accA.y + accB.y) * ri;
            accA.z = (accA.z + accB.z) * ri;
            accA.w = (accA.w + accB.w) * ri;
        }
        __half2 h01 = __floats2half2_rn(accA.x, accA.y);
        __half2 h23 = __floats2half2_rn(accA.z, accA.w);
        *(uint2*)(At + (warp * 4 + m) * 136 + 4 * lane) =
            make_uint2(*(unsigned*)&h01, *(unsigned*)&h23);
    }
    __syncthreads();   // A tile + W1h ready

    // --- wmma: H = A(48x128) @ W1(128x128), 24 tiles, 2 per warp ---
    {
        wmma::fragment<wmma::matrix_a, 16, 16, 16, __half, wmma::row_major> af;
        wmma::fragment<wmma::matrix_b, 16, 16, 16, __half, wmma::row_major> bf;
        wmma::fragment<wmma::accumulator, 16, 16, 16, float> cf;
        #pragma unroll
        for (int t = warp; t < 24; t += 12) {
            int mi = t >> 3, ni = t & 7;
            wmma::fill_fragment(cf, 0.0f);
            #pragma unroll
            for (int k0 = 0; k0 < 8; k0++) {
                wmma::load_matrix_sync(af, At + (mi * 16) * 136 + k0 * 16, 136);
                wmma::load_matrix_sync(bf, W1h + (k0 * 16) * 136 + ni * 16, 136);
                wmma::mma_sync(cf, af, bf, cf);
            }
            wmma::store_matrix_sync(Hs + (mi * 16) * 132 + ni * 16, cf, 132,
                                    wmma::mem_row_major);
        }
    }
    __syncthreads();   // H ready

    // --- epilogue: h = relu(H + b1); p = h @ W2; warp-reduce; *rs_out -> y ---
    float4 bb = ((const float4*)b1s)[lane];
    float2 w0 = ((float2*)W2s)[4 * lane + 0], w1 = ((float2*)W2s)[4 * lane + 1];
    float2 w2 = ((float2*)W2s)[4 * lane + 2], w3 = ((float2*)W2s)[4 * lane + 3];
    float p0[4], p1[4];
    #pragma unroll
    for (int m = 0; m < 4; m++) {
        float4 h = *(float4*)(Hs + (warp * 4 + m) * 132 + 4 * lane);
        float h0 = fmaxf(h.x + bb.x, 0.f), h1 = fmaxf(h.y + bb.y, 0.f);
        float h2 = fmaxf(h.z + bb.z, 0.f), h3 = fmaxf(h.w + bb.w, 0.f);
        p0[m] = h0 * w0.x + h1 * w1.x + h2 * w2.x + h3 * w3.x;
        p1[m] = h0 * w0.y + h1 * w1.y + h2 * w2.y + h3 * w3.y;
    }
    #pragma unroll
    for (int off = 16; off; off >>= 1) {
        #pragma unroll
        for (int m = 0; m < 4; m++) {
            p0[m] += __shfl_xor_sync(0xffffffffu, p0[m], off);
            p1[m] += __shfl_xor_sync(0xffffffffu, p1[m], off);
        }
    }
    if (lane == 0) {
        float2* y2 = (float2*)g_y;
        #pragma unroll
        for (int m = 0; m < 4; m++) {
            int node = i0 + m;
            if (node < N_NODES) {
                float ro = g_rs_out[node];
                y2[node] = make_float2(p0[m] * ro, p1[m] * ro);
            }
        }
    }
}

// ---------------- layer-2: CSR gather of y + finalize ------------------------
__global__ void k_out(float* __restrict__ out, const float* __restrict__ b2) {
    int i = blockIdx.x * blockDim.x + threadIdx.x;
    if (i >= N_NODES) return;
    int beg = __ldg(&g_rowp[i]), end = __ldg(&g_rowp[i + 1]);
    const float2* y2 = (const float2*)g_y;
    float s0 = 0.f, s1 = 0.f;
    int e = beg;
    for (; e + 2 <= end; e += 2) {
        int a = __ldg(&g_csr[e]), b = __ldg(&g_csr[e + 1]);
        float2 va = y2[a], vb = y2[b];
        s0 += va.x + vb.x;
        s1 += va.y + vb.y;
    }
    if (e < end) {
        float2 va = y2[__ldg(&g_csr[e])];
        s0 += va.x; s1 += va.y;
    }
    float ri = g_rs_in[i];
    ((float2*)out)[i] = make_float2(s0 * ri + __ldg(&b2[0]),
                                    s1 * ri + __ldg(&b2[1]));
}

// ---------------- launch ------------------------------------------------------
extern "C" void kernel_launch(void* const* d_in, const int* in_sizes, int n_in,
                              void* d_out, int out_size) {
    const float* in_feat = (const float*)d_in[0];
    const int*   src     = (const int*)d_in[1];
    const int*   dst     = (const int*)d_in[2];
    const float* W1      = (const float*)d_in[3];
    const float* b1      = (const float*)d_in[4];
    const float* W2      = (const float*)d_in[5];
    const float* b2      = (const float*)d_in[6];
    float*       out     = (float*)d_out;

    const int T = 256;
    cudaFuncSetAttribute(k_fused1, cudaFuncAttributeMaxDynamicSharedMemorySize, SM_F1_TOTAL);

    k_zero<<<(N_NODES + T - 1) / T, T>>>(W1);
    k_deg<<<(N_EDGES / 4 + T - 1) / T, T>>>((const int4*)src, (const int4*)dst);
    k_scan_block<<<NB_SCAN, 1024>>>();
    k_scan_fin<<<NB_SCAN, 1024>>>();
    k_prep<<<NB_PREP, T>>>((const float4*)in_feat, (const int4*)src, (const int4*)dst);
    k_fused1<<<NB_F1, TB_F1, SM_F1_TOTAL>>>(b1, W2);
    k_out<<<(N_NODES + T - 1) / T, T>>>(out, b2);
}